// round 7
// baseline (speedup 1.0000x reference)
#include <cuda_runtime.h>

#define N_HALF 4096
#define TWO_N  8192
#define D      8
#define NT     16                    // row/col tiles of 512
#define RT     512
#define BT     128                   // threads per block
#define ROWS_PT 4                    // rows per thread (RT = 4*BT)
#define CSPLIT 8                     // column octants per tile
#define CT     64                    // columns per block
#define NSLOT  (NT * CSPLIT)         // 128 partial slots per row
#define NPAIR  (NT * (NT + 1) / 2)   // 136 tile pairs
#define NBLK   (NPAIR * CSPLIT)      // 1088 blocks

#define LN2_F          0.6931471805599453f
#define HALF_LN2SQ_F   0.24022650695910072f   // ln2^2 / 2
#define HALF_LN2_F     0.34657359027997264f   // ln2 / 2
#define BOUNDARY_F     0.99999f

// __device__ scratch (allocation-free rule)
__device__ float        g_denom[NSLOT * TWO_N];   // 4 MB partials
__device__ float        g_partial[256];
__device__ unsigned int g_cnt;                     // zero-init at load

typedef unsigned long long u64;

__device__ __forceinline__ float fast_sqrt(float x) { float y; asm("sqrt.approx.f32 %0, %1;" : "=f"(y) : "f"(x)); return y; }
__device__ __forceinline__ float fast_lg2(float x)  { float y; asm("lg2.approx.f32 %0, %1;"  : "=f"(y) : "f"(x)); return y; }
__device__ __forceinline__ float fast_ex2(float x)  { float y; asm("ex2.approx.f32 %0, %1;"  : "=f"(y) : "f"(x)); return y; }

__device__ __forceinline__ u64 pack2(float lo, float hi) {
    u64 r; asm("mov.b64 %0, {%1,%2};" : "=l"(r) : "f"(lo), "f"(hi)); return r;
}
__device__ __forceinline__ void unpack2(u64 v, float& lo, float& hi) {
    asm("mov.b64 {%0,%1}, %2;" : "=f"(lo), "=f"(hi) : "l"(v));
}
__device__ __forceinline__ u64 fma2(u64 a, u64 b, u64 c) {
    u64 r; asm("fma.rn.f32x2 %0, %1, %2, %3;" : "=l"(r) : "l"(a), "l"(b), "l"(c)); return r;
}
__device__ __forceinline__ u64 mul2(u64 a, u64 b) {
    u64 r; asm("mul.rn.f32x2 %0, %1, %2;" : "=l"(r) : "l"(a), "l"(b)); return r;
}
__device__ __forceinline__ u64 add2(u64 a, u64 b) {
    u64 r; asm("add.rn.f32x2 %0, %1, %2;" : "=l"(r) : "l"(a), "l"(b)); return r;
}
__device__ __forceinline__ float neg_bits(float x) {
    return __int_as_float(__float_as_int(x) ^ 0x80000000);   // ALU pipe
}

// Packed constants bundle (hoisted once per kernel, passed by value -> regs)
struct ChainConst {
    u64 c10;   // {1, 0}   (+1 fold into dot)
    u64 m11;   // {-1, -1}
    u64 cc1;   // {ln2^2/2, ln2^2/2}
    u64 cc0;   // {ln2/2,  ln2/2}
    u64 m22;   // {-2, -2}
    u64 p22;   // {+2, +2}
};
__device__ __forceinline__ ChainConst make_cc() {
    ChainConst k;
    k.c10 = pack2(1.0f, 0.0f);
    k.m11 = pack2(-1.0f, -1.0f);
    k.cc1 = pack2(HALF_LN2SQ_F, HALF_LN2SQ_F);
    k.cc0 = pack2(HALF_LN2_F, HALF_LN2_F);
    k.m22 = pack2(-2.0f, -2.0f);
    k.p22 = pack2(2.0f, 2.0f);
    return k;
}

// ---- shared building blocks (identical in both kernels: bit-exact self-term)
__device__ __forceinline__ void load_point(const float* __restrict__ zi,
                                           const float* __restrict__ zj,
                                           int i, float4& a, float4& b) {
    const float* src = (i < N_HALF) ? (zi + (size_t)i * D)
                                    : (zj + (size_t)(i - N_HALF) * D);
    a = *reinterpret_cast<const float4*>(src);
    b = *reinterpret_cast<const float4*>(src + 4);
}

__device__ __forceinline__ float raw8(const float4& a, const float4& b) {
    float d = __fmul_rn(a.x, a.x);
    d = fmaf(a.y, a.y, d); d = fmaf(a.z, a.z, d); d = fmaf(a.w, a.w, d);
    d = fmaf(b.x, b.x, d); d = fmaf(b.y, b.y, d); d = fmaf(b.z, b.z, d);
    d = fmaf(b.w, b.w, d);
    return d;
}

// row-side augmented vector: a = [-4*inv*z(8); 2*inv*raw; 2*inv]
__device__ __forceinline__ void build_a(const float4& a, const float4& b, u64 A[5]) {
    float raw = raw8(a, b);
    float inv = 1.0f / (1.0f - fminf(raw, BOUNDARY_F));
    float m   = __fmul_rn(-4.0f, inv);
    A[0] = pack2(__fmul_rn(m, a.x), __fmul_rn(m, a.y));
    A[1] = pack2(__fmul_rn(m, a.z), __fmul_rn(m, a.w));
    A[2] = pack2(__fmul_rn(m, b.x), __fmul_rn(m, b.y));
    A[3] = pack2(__fmul_rn(m, b.z), __fmul_rn(m, b.w));
    float i2 = __fadd_rn(inv, inv);
    A[4] = pack2(__fmul_rn(i2, raw), i2);
}

// col-side augmented vector: b = [inv*z(8); inv; inv*raw]
__device__ __forceinline__ void build_b(const float4& a, const float4& b, u64 B[5]) {
    float raw = raw8(a, b);
    float inv = 1.0f / (1.0f - fminf(raw, BOUNDARY_F));
    B[0] = pack2(__fmul_rn(inv, a.x), __fmul_rn(inv, a.y));
    B[1] = pack2(__fmul_rn(inv, a.z), __fmul_rn(inv, a.w));
    B[2] = pack2(__fmul_rn(inv, b.x), __fmul_rn(inv, b.y));
    B[3] = pack2(__fmul_rn(inv, b.z), __fmul_rn(inv, b.w));
    B[4] = pack2(inv, __fmul_rn(inv, raw));
}

// x = max(1 + a.b, 1)
__device__ __forceinline__ float dotx(const u64 A[5], const u64 B[5], u64 c10) {
    u64 s = fma2(A[4], B[4], c10);
    s = fma2(A[0], B[0], s);
    s = fma2(A[1], B[1], s);
    s = fma2(A[2], B[2], s);
    s = fma2(A[3], B[3], s);
    float lo, hi;
    unpack2(s, lo, hi);
    return fmaxf(__fadd_rn(lo, hi), 1.0f);   // FMNMX on alu pipe
}

// Packed chain: e = exp(2*sim) for TWO pairs at once.
// Bit-identical to the scalar sqrt/lg2/newton-rcp/ex2 chain (rn per lane).
__device__ __forceinline__ void chain_e2(float x0, float x1, const ChainConst& k,
                                         float& e0, float& e1) {
    u64 x01 = pack2(x0, x1);
    u64 xx  = fma2(x01, x01, k.m11);            // x^2 - 1  (>= 0)
    float q0, q1; unpack2(xx, q0, q1);
    float s0 = fast_sqrt(q0);                    // MUFU
    float s1 = fast_sqrt(q1);                    // MUFU
    float l0 = fast_lg2(__fadd_rn(x0, s0));      // MUFU
    float l1 = fast_lg2(__fadd_rn(x1, s1));      // MUFU
    u64 dn = fma2(pack2(l0, l1), k.cc1, k.cc0);  // (1+dist)*ln2/2
    float d0, d1; unpack2(dn, d0, d1);
    u64 y = pack2(__int_as_float(0x7EF311C3 - __float_as_int(d0)),   // IADD alu
                  __int_as_float(0x7EF311C3 - __float_as_int(d1)));
    u64 t = fma2(dn, y, k.m22);                  // d*y - 2
    y = mul2(y, t);                              // = -(y*(2-d*y))
    t = fma2(dn, y, k.p22);                      // = 2 - d*w1
    y = mul2(y, t);                              // = -r  (negated reciprocal)
    float r0, r1; unpack2(y, r0, r1);
    e0 = fast_ex2(neg_bits(r0));                 // MUFU
    e1 = fast_ex2(neg_bits(r1));                 // MUFU
}

// sim = 1/(1+arcosh(x))  (finalize positives only; 2N evals)
__device__ __forceinline__ float chain_sim(float x) {
    float x2 = fmaf(x, x, -1.0f);
    float s  = fast_sqrt(x2);
    float l  = fast_lg2(__fadd_rn(x, s));
    float d  = fmaf(l, LN2_F, 1.0f);
    float y  = __int_as_float(0x7EF311C3 - __float_as_int(d));
    y = __fmul_rn(y, fmaf(-d, y, 2.0f));
    y = __fmul_rn(y, fmaf(-d, y, 2.0f));
    return y;
}

// ---------------------------------------------------------------------------
// Kernel 1: symmetric pairwise tiles -> partial softmax denominators
// grid = 1088, block = 128 (4 rows/thread, 64 columns/block)
// ---------------------------------------------------------------------------
__global__ void __launch_bounds__(BT)
pair_kernel(const float* __restrict__ zi, const float* __restrict__ zj) {
    __shared__ u64   sb[5][CT];     // column augmented vectors (SoA)
    __shared__ float wacc[4][CT];   // per-warp column sums

    const int t    = threadIdx.x;
    const int lane = t & 31;
    const int w    = t >> 5;
    const int nxt  = (lane + 1) & 31;

    // decode (a, b, h)
    int p = blockIdx.x >> 3;
    int h = blockIdx.x & 7;
    int a = 0, rem = p;
    while (rem >= NT - a) { rem -= NT - a; ++a; }
    int b = a + rem;
    const bool diag = (a == b);
    const int jbase = b * RT + h * CT;

    // stage 64 columns
    if (t < CT) {
        float4 ca, cb;
        load_point(zi, zj, jbase + t, ca, cb);
        u64 B[5];
        build_b(ca, cb, B);
        sb[0][t] = B[0]; sb[1][t] = B[1]; sb[2][t] = B[2];
        sb[3][t] = B[3]; sb[4][t] = B[4];
    }

    // build 4 row vectors
    u64 A[ROWS_PT][5];
    #pragma unroll
    for (int r = 0; r < ROWS_PT; ++r) {
        float4 ra, rb;
        load_point(zi, zj, a * RT + r * BT + t, ra, rb);
        build_a(ra, rb, A[r]);
    }

    const ChainConst K = make_cc();

    __syncthreads();

    u64 racc01 = pack2(0.0f, 0.0f);
    u64 racc23 = pack2(0.0f, 0.0f);

    if (diag) {
        #pragma unroll 4
        for (int c = 0; c < CT; ++c) {                    // broadcast LDS
            u64 B[5] = { sb[0][c], sb[1][c], sb[2][c], sb[3][c], sb[4][c] };
            float x0 = dotx(A[0], B, K.c10);
            float x1 = dotx(A[1], B, K.c10);
            float x2 = dotx(A[2], B, K.c10);
            float x3 = dotx(A[3], B, K.c10);
            float e0, e1, e2, e3;
            chain_e2(x0, x1, K, e0, e1);
            chain_e2(x2, x3, K, e2, e3);
            racc01 = add2(racc01, pack2(e0, e1));
            racc23 = add2(racc23, pack2(e2, e3));
        }
    } else {
        #pragma unroll
        for (int g = 0; g < CT / 32; ++g) {
            float cacc = 0.0f;                            // systolic ring acc
            #pragma unroll 4
            for (int k = 0; k < 32; ++k) {
                int c = (g << 5) + ((lane + k) & 31);     // conflict-free
                u64 B[5] = { sb[0][c], sb[1][c], sb[2][c], sb[3][c], sb[4][c] };
                float x0 = dotx(A[0], B, K.c10);
                float x1 = dotx(A[1], B, K.c10);
                float x2 = dotx(A[2], B, K.c10);
                float x3 = dotx(A[3], B, K.c10);
                float e0, e1, e2, e3;
                chain_e2(x0, x1, K, e0, e1);
                chain_e2(x2, x3, K, e2, e3);
                racc01 = add2(racc01, pack2(e0, e1));
                racc23 = add2(racc23, pack2(e2, e3));
                cacc += ((e0 + e1) + (e2 + e3));
                cacc = __shfl_sync(0xFFFFFFFFu, cacc, nxt, 32);
            }
            wacc[w][(g << 5) + lane] = cacc;              // lane holds col 'lane'
        }
    }

    // row-side partials: slot (b, h)
    float r0, r1, r2, r3;
    unpack2(racc01, r0, r1);
    unpack2(racc23, r2, r3);
    const size_t rbase = (size_t)(b * CSPLIT + h) * TWO_N + a * RT + t;
    g_denom[rbase]                   = r0;
    g_denom[rbase + (size_t)BT]      = r1;
    g_denom[rbase + (size_t)2 * BT]  = r2;
    g_denom[rbase + (size_t)3 * BT]  = r3;

    // column-side partials: slot (a, h)
    if (!diag) {
        __syncthreads();
        if (t < CT) {
            float c = ((wacc[0][t] + wacc[1][t]) + (wacc[2][t] + wacc[3][t]));
            g_denom[(size_t)(a * CSPLIT + h) * TWO_N + jbase + t] = c;
        }
    }
}

// ---------------------------------------------------------------------------
// Kernel 2: denom combine (8 threads/row x 16 slots) + positives + full reduce
// grid = 256, block = 256 (32 rows per block); last block finalizes
// ---------------------------------------------------------------------------
__global__ void __launch_bounds__(256)
fin_kernel(const float* __restrict__ zi, const float* __restrict__ zj,
           float* __restrict__ out) {
    __shared__ float sacc[8][32];
    const int t = threadIdx.x;
    const int r = t & 31;          // row within block
    const int g = t >> 5;          // slot group (16 slots each)
    const int i = blockIdx.x * 32 + r;

    float d = 0.0f;
    #pragma unroll
    for (int c = 0; c < 16; ++c)
        d += g_denom[(size_t)(g * 16 + c) * TWO_N + i];
    sacc[g][r] = d;
    __syncthreads();

    if (g == 0) {                  // warp 0 finishes the 32 rows
        float denom = 0.0f;
        #pragma unroll
        for (int ww = 0; ww < 8; ++ww) denom += sacc[ww][r];

        const ChainConst K = make_cc();

        float4 ua, ub;
        load_point(zi, zj, i, ua, ub);
        u64 Ai[5], Bi[5];
        build_a(ua, ub, Ai);
        build_b(ua, ub, Bi);
        float xs = dotx(Ai, Bi, K.c10);
        float es0, es1;
        chain_e2(xs, xs, K, es0, es1);            // identical packed path
        denom -= es0;                             // bit-exact self cancel

        const int pp = (i < N_HALF) ? (i + N_HALF) : (i - N_HALF);
        float4 va, vb;
        load_point(zi, zj, pp, va, vb);
        u64 Bp[5];
        build_b(va, vb, Bp);
        float sim = chain_sim(dotx(Ai, Bp, K.c10));

        float loss = fast_lg2(denom) * LN2_F - 2.0f * sim;
        #pragma unroll
        for (int s = 16; s > 0; s >>= 1)
            loss += __shfl_xor_sync(0xFFFFFFFFu, loss, s);

        unsigned tk = 0u;
        if (r == 0) {
            g_partial[blockIdx.x] = loss;
            __threadfence();
            tk = atomicAdd(&g_cnt, 1u) + 1u;
        }
        tk = __shfl_sync(0xFFFFFFFFu, tk, 0);
        if (tk == 256u) {                          // last block finalizes
            __threadfence();
            float v = 0.0f;
            #pragma unroll
            for (int j = 0; j < 8; ++j) v += g_partial[r + j * 32];
            #pragma unroll
            for (int s = 16; s > 0; s >>= 1)
                v += __shfl_xor_sync(0xFFFFFFFFu, v, s);
            if (r == 0) {
                out[0] = v / (float)TWO_N;
                g_cnt = 0;                         // reset for next replay
            }
        }
    }
}

// ---------------------------------------------------------------------------
extern "C" void kernel_launch(void* const* d_in, const int* in_sizes, int n_in,
                              void* d_out, int out_size) {
    const float* zi = (const float*)d_in[0];
    const float* zj = (const float*)d_in[1];
    float* out = (float*)d_out;

    pair_kernel<<<NBLK, BT>>>(zi, zj);
    fin_kernel<<<256, 256>>>(zi, zj, out);
}